// round 11
// baseline (speedup 1.0000x reference)
#include <cuda_runtime.h>
#include <cuda_fp16.h>
#include <cstdint>

// ---------------------------------------------------------------------------
// 4D ConvTranspose stride2 K=3^4 as 16 parity-class GEMMs on tensor cores
// (ldmatrix + mma.sync m16n8k16 f16, fp32 accum).
//   D[sp=256, co=64] += X[sp, k]·W[co, k],  k = (tap t, ci),  K = 64*T
// R11: staging via cp.async.bulk (1 op per 128B row, 8x fewer LSU ops than
// cpa16) with mbarrier complete_tx tracking; smem rows pitch 144B so
// ldmatrix is conflict-free without XOR swizzle. fp16 single-term
// (rel_err 2.9e-4, validated). Ping-pong double buffer across taps.
// ---------------------------------------------------------------------------

#define XM 20736            // 12^4 input spatial points
#define OSB 25000000LL
#define OSC 390625
#define OS1 15625
#define OS2 625
#define OS3 25

#define PITCH 144           // 128B row + 16B skew -> ldsm conflict-free

// prepped operands
__device__ __align__(16) __half g_w16[81*64*64];   // [kidx][co][ci]
__device__ __align__(16) __half g_x16[4L*XM*64];   // [b][m_lin][ci]
__device__ __align__(128) __half g_zero[64];       // zero row (static zero-init)

// dynamic SMEM layout
#define SM_A    0            // 2 bufs x 256 rows x 144B = 73728
#define SM_B    73728        // 2 bufs x 64 rows x 144B = 18432
#define SM_OFFS 92160        // u16[16*256] = 8192
#define SM_BIAS 100352       // float[64]
#define SM_KOF  100608       // int[16]
#define SM_DD   100672       // char[16][4]
#define SM_MBAR 100736       // 2 x u64 mbarriers
#define SM_TOTAL 100768

#define STAGE_BYTES 40960u   // 256*128 (A) + 64*128 (B)

// ---------------- prep kernels ----------------
__global__ void wq_prep(const float* __restrict__ w) {
    int idx = blockIdx.x * 256 + threadIdx.x;
    if (idx >= 331776) return;                 // 64*64*81
    int ci = idx / 5184;
    int r  = idx - ci * 5184;
    int co = r / 81;
    int k  = r - co * 81;
    g_w16[(k * 64 + co) * 64 + ci] = __float2half(w[idx]);
}

__global__ void xq_prep(const float* __restrict__ x) {
    __shared__ float s[64][33];
    int b = blockIdx.y, m0 = blockIdx.x * 32, tid = threadIdx.x;
    for (int i = tid; i < 2048; i += 256) {
        int ci = i >> 5, mm = i & 31;
        s[ci][mm] = x[((size_t)(b * 64 + ci)) * XM + m0 + mm];
    }
    __syncthreads();
    int m = tid >> 3, q = tid & 7;
    union { __half a[8]; uint4 v; } hv;
    #pragma unroll
    for (int j = 0; j < 8; j++)
        hv.a[j] = __float2half(s[q * 8 + j][m]);
    *(uint4*)(g_x16 + ((size_t)b * XM + m0 + m) * 64 + q * 8) = hv.v;
}

// ---------------- ptx helpers ----------------
__device__ __forceinline__ uint32_t smem_u32(const void* p) {
    uint32_t a;
    asm("{ .reg .u64 t; cvta.to.shared.u64 t, %1; cvt.u32.u64 %0, t; }" : "=r"(a) : "l"(p));
    return a;
}
__device__ __forceinline__ void ldsm4(uint32_t r[4], uint32_t addr) {
    asm volatile("ldmatrix.sync.aligned.m8n8.x4.shared.b16 {%0,%1,%2,%3}, [%4];"
                 : "=r"(r[0]), "=r"(r[1]), "=r"(r[2]), "=r"(r[3]) : "r"(addr));
}
__device__ __forceinline__ void mma_f16(float c[4], const uint32_t a[4],
                                        uint32_t b0, uint32_t b1) {
    asm volatile("mma.sync.aligned.m16n8k16.row.col.f32.f16.f16.f32 "
                 "{%0,%1,%2,%3}, {%4,%5,%6,%7}, {%8,%9}, {%0,%1,%2,%3};"
                 : "+f"(c[0]), "+f"(c[1]), "+f"(c[2]), "+f"(c[3])
                 : "r"(a[0]), "r"(a[1]), "r"(a[2]), "r"(a[3]), "r"(b0), "r"(b1));
}
__device__ __forceinline__ void bulk128(uint32_t dst, const void* src, uint32_t mbar) {
    asm volatile("cp.async.bulk.shared::cta.global.mbarrier::complete_tx::bytes "
                 "[%0], [%1], 128, [%2];"
                 :: "r"(dst), "l"(src), "r"(mbar) : "memory");
}
__device__ __forceinline__ void mbar_init(uint32_t mbar, uint32_t cnt) {
    asm volatile("mbarrier.init.shared::cta.b64 [%0], %1;" :: "r"(mbar), "r"(cnt) : "memory");
}
__device__ __forceinline__ void mbar_expect(uint32_t mbar, uint32_t bytes) {
    asm volatile("mbarrier.arrive.expect_tx.shared::cta.b64 _, [%0], %1;"
                 :: "r"(mbar), "r"(bytes) : "memory");
}
__device__ __forceinline__ void mbar_wait(uint32_t mbar, uint32_t ph) {
    asm volatile(
        "{\n\t.reg .pred P;\n"
        "W_%=:\n\t"
        "mbarrier.try_wait.parity.acquire.cta.shared::cta.b64 P, [%0], %1, 0x989680;\n\t"
        "@!P bra W_%=;\n\t}" :: "r"(mbar), "r"(ph) : "memory");
}

// ---------------- main kernel ----------------
__global__ __launch_bounds__(256) void ct4d_mma(
    const float* __restrict__ bias, float* __restrict__ out)
{
    extern __shared__ char smem[];
    const int tid = threadIdx.x, lane = tid & 31, wrp = tid >> 5;
    const int c = blockIdx.z, b = blockIdx.y, tile = blockIdx.x;
    const int p1 = (c >> 3) & 1, p2 = (c >> 2) & 1, p3 = (c >> 1) & 1, p4 = c & 1;
    const int n1 = 13 - p1, n2 = 13 - p2, n3 = 13 - p3, n4 = 13 - p4;
    const int Ntot = n1 * n2 * n3 * n4;
    if (tile * 256 >= Ntot) return;
    const int lgT = 4 - p1 - p2 - p3 - p4;
    const int T = 1 << lgT;

    const uint32_t sb = smem_u32(smem);
    int*          kof  = (int*)(smem + SM_KOF);
    signed char (*dd)[4] = (signed char(*)[4])(smem + SM_DD);
    uint16_t*     offs = (uint16_t*)(smem + SM_OFFS);
    float*        bs   = (float*)(smem + SM_BIAS);
    const uint32_t mb0 = sb + SM_MBAR, mb1 = sb + SM_MBAR + 8;

    if (tid == 0) { mbar_init(mb0, 1); mbar_init(mb1, 1); }
    if (tid < T) {
        int rem = tid, pp[4] = {p1, p2, p3, p4}, d[4], k[4];
        #pragma unroll
        for (int i = 0; i < 4; i++) {
            if (!pp[i]) { d[i] = rem & 1; rem >>= 1; k[i] = 2 * d[i]; }
            else        { d[i] = 0;                  k[i] = 1; }
        }
        kof[tid] = ((k[0] * 3 + k[1]) * 3 + k[2]) * 3 + k[3];
        dd[tid][0] = d[0]; dd[tid][1] = d[1]; dd[tid][2] = d[2]; dd[tid][3] = d[3];
    }
    if (tid < 64) bs[tid] = bias[tid];
    __syncthreads();

    // gather offsets per (tap, sp row); 0xFFFF = OOB/pad
    {
        int g = tile * 256 + tid;
        int valid = g < Ntot, m1 = 0, m2 = 0, m3 = 0, m4 = 0;
        if (valid) { m4 = g % n4; int q = g / n4; m3 = q % n3; q /= n3; m2 = q % n2; m1 = q / n2; }
        for (int t = 0; t < T; t++) {
            int off = 0xFFFF;
            if (valid) {
                int a1 = m1 - dd[t][0], a2 = m2 - dd[t][1], a3 = m3 - dd[t][2], a4 = m4 - dd[t][3];
                if (((unsigned)a1 < 12u) & ((unsigned)a2 < 12u) & ((unsigned)a3 < 12u) & ((unsigned)a4 < 12u))
                    off = ((a1 * 12 + a2) * 12 + a3) * 12 + a4;
            }
            offs[t * 256 + tid] = (uint16_t)off;
        }
    }
    __syncthreads();   // offs + mbar init visible before staging

    const __half* xb = g_x16 + (size_t)b * XM * 64;

    auto stage = [&](int t, int bf) {
        const uint32_t mb = bf ? mb1 : mb0;
        if (tid == 0) mbar_expect(mb, STAGE_BYTES);
        // A: one 128B row per thread
        {
            uint32_t off = offs[t * 256 + tid];
            const void* src = (off != 0xFFFFu) ? (const void*)(xb + (size_t)off * 64)
                                               : (const void*)g_zero;
            bulk128(sb + SM_A + bf * (256 * PITCH) + tid * PITCH, src, mb);
        }
        // B: one 128B row per thread for tid<64
        if (tid < 64)
            bulk128(sb + SM_B + bf * (64 * PITCH) + tid * PITCH,
                    g_w16 + (kof[t] * 64 + tid) * 64, mb);
    };

    float acc[2][8][4];
    #pragma unroll
    for (int i = 0; i < 2; i++)
        #pragma unroll
        for (int j = 0; j < 8; j++)
            #pragma unroll
            for (int q = 0; q < 4; q++) acc[i][j][q] = 0.f;

    stage(0, 0);
    uint32_t ph0 = 0, ph1 = 0;

    const int arow_s = lane & 15;
    const int aseg   = ((lane >> 4) & 1) * 16;
    const int brow_s = ((lane >> 4) & 1) * 8 + (lane & 7);
    const int bseg   = ((lane >> 3) & 1) * 16;

    for (int t = 0; t < T; t++) {
        const int bf = t & 1;
        if (t + 1 < T) stage(t + 1, bf ^ 1);
        if (bf) { mbar_wait(mb1, ph1); ph1 ^= 1; }
        else    { mbar_wait(mb0, ph0); ph0 ^= 1; }

        const uint32_t abase = sb + SM_A + bf * (256 * PITCH);
        const uint32_t bbase = sb + SM_B + bf * (64 * PITCH);

        #pragma unroll
        for (int kk = 0; kk < 4; kk++) {
            uint32_t Af[2][4];
            const uint32_t acol = kk * 32 + aseg;
            #pragma unroll
            for (int i = 0; i < 2; i++)
                ldsm4(Af[i], abase + (wrp * 32 + i * 16 + arow_s) * PITCH + acol);
            #pragma unroll
            for (int jp = 0; jp < 4; jp++) {
                uint32_t Bf[4];
                ldsm4(Bf, bbase + (jp * 16 + brow_s) * PITCH + kk * 32 + bseg);
                #pragma unroll
                for (int i = 0; i < 2; i++) {
                    mma_f16(acc[i][2 * jp],     Af[i], Bf[0], Bf[1]);
                    mma_f16(acc[i][2 * jp + 1], Af[i], Bf[2], Bf[3]);
                }
            }
        }
        if (t + 1 < T) __syncthreads();  // all warps done with bf before restage
    }

    // epilogue: bias, strided scatter into the class sub-grid
    float* ob = out + (size_t)b * OSB;
    const int gbase = tile * 256 + wrp * 32 + (lane >> 2);
    #pragma unroll
    for (int i = 0; i < 2; i++) {
        #pragma unroll
        for (int h = 0; h < 2; h++) {
            int g = gbase + i * 16 + h * 8;
            if (g >= Ntot) continue;
            int m4 = g % n4; int q = g / n4;
            int m3 = q % n3; q /= n3;
            int m2 = q % n2; int m1 = q / n2;
            long o = (long)(2 * m1 + p1) * OS1 + (2 * m2 + p2) * OS2 +
                     (2 * m3 + p3) * OS3 + (2 * m4 + p4);
            float* op = ob + o;
            #pragma unroll
            for (int j = 0; j < 8; j++) {
                int co = j * 8 + (lane & 3) * 2;
                op[(size_t)co * OSC]       = acc[i][j][2 * h]     + bs[co];
                op[(size_t)(co + 1) * OSC] = acc[i][j][2 * h + 1] + bs[co + 1];
            }
        }
    }
}

extern "C" void kernel_launch(void* const* d_in, const int* in_sizes, int n_in,
                              void* d_out, int out_size) {
    const float* x    = (const float*)d_in[0];
    const float* w    = (const float*)d_in[1];
    const float* bias = (const float*)d_in[2];
    float* out = (float*)d_out;

    cudaFuncSetAttribute(ct4d_mma, cudaFuncAttributeMaxDynamicSharedMemorySize, SM_TOTAL);

    wq_prep<<<1296, 256>>>(w);
    xq_prep<<<dim3(648, 4), 256>>>(x);
    // 112 = ceil(13^4 / 256); smaller classes early-exit surplus tiles.
    ct4d_mma<<<dim3(112, 4, 16), 256, SM_TOTAL>>>(bias, out);
}

// round 12
// speedup vs baseline: 1.1731x; 1.1731x over previous
#include <cuda_runtime.h>
#include <cuda_fp16.h>
#include <cstdint>

// ---------------------------------------------------------------------------
// 4D ConvTranspose stride2 K=3^4 as 16 parity-class GEMMs on tensor cores
// (ldmatrix + mma.sync m16n8k16 f16, fp32 accum).
//   D[sp=256, co=64] += X[sp, k]·W[co, k],  k = (tap t, ci),  K = 64*T
// R12: single __syncthreads per tap (stage(t+1) after the sync; the same
// barrier orders stage-t visibility AND compute(t-1) completion), cp.async
// wait moved a full tap from issue, prep kernels fused into one launch.
// fp16 single-term (rel_err 2.9e-4, validated), ping-pong buffers.
// ---------------------------------------------------------------------------

#define XM 20736            // 12^4 input spatial points
#define OSB 25000000LL
#define OSC 390625
#define OS1 15625
#define OS2 625
#define OS3 25

// prepped operands
__device__ __align__(16) __half g_w16[81*64*64];   // [kidx][co][ci]
__device__ __align__(16) __half g_x16[4L*XM*64];   // [b][m_lin][ci]

// dynamic SMEM: ping-pong buffers. Rows 128B, XOR-swizzled.
#define SM_A    0            // 2 bufs x 256 rows x 128B = 65536
#define SM_B    65536        // 2 bufs x 64 rows x 128B = 16384
#define SM_OFFS 81920        // u16[16*256] = 8192
#define SM_BIAS 90112        // float[64]
#define SM_KOF  90368        // int[16]
#define SM_DD   90432        // char[16][4]
#define SM_TOTAL 90496

#define SWZ(o) ((o) ^ (((o) >> 3) & 0x70))

// ---------------- fused prep kernel ----------------
// blocks [0, 1296): weight transpose+cast; blocks [1296, 3888): x transpose+cast
__global__ void prep_all(const float* __restrict__ w, const float* __restrict__ x) {
    if (blockIdx.x < 1296) {
        int idx = blockIdx.x * 256 + threadIdx.x;
        if (idx >= 331776) return;                 // 64*64*81
        int ci = idx / 5184;
        int r  = idx - ci * 5184;
        int co = r / 81;
        int k  = r - co * 81;
        g_w16[(k * 64 + co) * 64 + ci] = __float2half(w[idx]);
    } else {
        __shared__ float s[64][33];
        int q = blockIdx.x - 1296;                 // 0..2591
        int b = q / 648, m0 = (q - b * 648) * 32, tid = threadIdx.x;
        for (int i = tid; i < 2048; i += 256) {
            int ci = i >> 5, mm = i & 31;
            s[ci][mm] = x[((size_t)(b * 64 + ci)) * XM + m0 + mm];
        }
        __syncthreads();
        int m = tid >> 3, qq = tid & 7;
        union { __half a[8]; uint4 v; } hv;
        #pragma unroll
        for (int j = 0; j < 8; j++)
            hv.a[j] = __float2half(s[qq * 8 + j][m]);
        *(uint4*)(g_x16 + ((size_t)b * XM + m0 + m) * 64 + qq * 8) = hv.v;
    }
}

// ---------------- ptx helpers ----------------
__device__ __forceinline__ uint32_t smem_u32(const void* p) {
    uint32_t a;
    asm("{ .reg .u64 t; cvta.to.shared.u64 t, %1; cvt.u32.u64 %0, t; }" : "=r"(a) : "l"(p));
    return a;
}
__device__ __forceinline__ void ldsm4(uint32_t r[4], uint32_t addr) {
    asm volatile("ldmatrix.sync.aligned.m8n8.x4.shared.b16 {%0,%1,%2,%3}, [%4];"
                 : "=r"(r[0]), "=r"(r[1]), "=r"(r[2]), "=r"(r[3]) : "r"(addr));
}
__device__ __forceinline__ void mma_f16(float c[4], const uint32_t a[4],
                                        uint32_t b0, uint32_t b1) {
    asm volatile("mma.sync.aligned.m16n8k16.row.col.f32.f16.f16.f32 "
                 "{%0,%1,%2,%3}, {%4,%5,%6,%7}, {%8,%9}, {%0,%1,%2,%3};"
                 : "+f"(c[0]), "+f"(c[1]), "+f"(c[2]), "+f"(c[3])
                 : "r"(a[0]), "r"(a[1]), "r"(a[2]), "r"(a[3]), "r"(b0), "r"(b1));
}
__device__ __forceinline__ void cpa16(uint32_t dst, const void* src, bool pred) {
    int sz = pred ? 16 : 0;
    asm volatile("cp.async.cg.shared.global [%0], [%1], 16, %2;"
                 :: "r"(dst), "l"(src), "r"(sz) : "memory");
}

// ---------------- main kernel ----------------
__global__ __launch_bounds__(256) void ct4d_mma(
    const float* __restrict__ bias, float* __restrict__ out)
{
    extern __shared__ char smem[];
    const int tid = threadIdx.x, lane = tid & 31, wrp = tid >> 5;
    const int c = blockIdx.z, b = blockIdx.y, tile = blockIdx.x;
    const int p1 = (c >> 3) & 1, p2 = (c >> 2) & 1, p3 = (c >> 1) & 1, p4 = c & 1;
    const int n1 = 13 - p1, n2 = 13 - p2, n3 = 13 - p3, n4 = 13 - p4;
    const int Ntot = n1 * n2 * n3 * n4;
    if (tile * 256 >= Ntot) return;
    const int lgT = 4 - p1 - p2 - p3 - p4;
    const int T = 1 << lgT;

    const uint32_t sb = smem_u32(smem);
    int*          kof  = (int*)(smem + SM_KOF);
    signed char (*dd)[4] = (signed char(*)[4])(smem + SM_DD);
    uint16_t*     offs = (uint16_t*)(smem + SM_OFFS);
    float*        bs   = (float*)(smem + SM_BIAS);

    if (tid < T) {
        int rem = tid, pp[4] = {p1, p2, p3, p4}, d[4], k[4];
        #pragma unroll
        for (int i = 0; i < 4; i++) {
            if (!pp[i]) { d[i] = rem & 1; rem >>= 1; k[i] = 2 * d[i]; }
            else        { d[i] = 0;                  k[i] = 1; }
        }
        kof[tid] = ((k[0] * 3 + k[1]) * 3 + k[2]) * 3 + k[3];
        dd[tid][0] = d[0]; dd[tid][1] = d[1]; dd[tid][2] = d[2]; dd[tid][3] = d[3];
    }
    if (tid < 64) bs[tid] = bias[tid];
    __syncthreads();

    // gather offsets per (tap, sp row); 0xFFFF = OOB/pad
    {
        int g = tile * 256 + tid;
        int valid = g < Ntot, m1 = 0, m2 = 0, m3 = 0, m4 = 0;
        if (valid) { m4 = g % n4; int q = g / n4; m3 = q % n3; q /= n3; m2 = q % n2; m1 = q / n2; }
        for (int t = 0; t < T; t++) {
            int off = 0xFFFF;
            if (valid) {
                int a1 = m1 - dd[t][0], a2 = m2 - dd[t][1], a3 = m3 - dd[t][2], a4 = m4 - dd[t][3];
                if (((unsigned)a1 < 12u) & ((unsigned)a2 < 12u) & ((unsigned)a3 < 12u) & ((unsigned)a4 < 12u))
                    off = ((a1 * 12 + a2) * 12 + a3) * 12 + a4;
            }
            offs[t * 256 + tid] = (uint16_t)off;
        }
    }
    __syncthreads();   // offs visible to all threads before staging

    const __half* xb = g_x16 + (size_t)b * XM * 64;

    auto stage = [&](int t, int bf) {
        // B: 64 co rows x 128B. 256 threads: 4 threads/row x 2 segs each.
        {
            const int kb = kof[t] * 64;
            int r = tid >> 2, q = tid & 3;
            #pragma unroll
            for (int s = 0; s < 2; s++) {
                int seg = q * 2 + s;
                uint32_t so = bf * 8192 + SWZ(r * 128 + seg * 16);
                cpa16(sb + SM_B + so, g_w16 + (kb + r) * 64 + seg * 8, true);
            }
        }
        // A: 256 sp rows x 128B (8 threads/row, 32 rows/pass, 8 passes)
        {
            const uint16_t* ot = offs + t * 256;
            int q8 = tid & 7, rsub = tid >> 3;
            #pragma unroll
            for (int rb = 0; rb < 256; rb += 32) {
                int r = rb + rsub;
                uint32_t off = ot[r];
                bool ok = off != 0xFFFFu;
                uint32_t so = bf * 32768 + SWZ(r * 128 + q8 * 16);
                cpa16(sb + SM_A + so, xb + (size_t)(ok ? off : 0) * 64 + q8 * 8, ok);
            }
        }
        asm volatile("cp.async.commit_group;" ::: "memory");
    };

    float acc[2][8][4];
    #pragma unroll
    for (int i = 0; i < 2; i++)
        #pragma unroll
        for (int j = 0; j < 8; j++)
            #pragma unroll
            for (int q = 0; q < 4; q++) acc[i][j][q] = 0.f;

    stage(0, 0);

    const int arow_s = lane & 15;
    const int aseg   = ((lane >> 4) & 1) * 16;
    const int brow_s = ((lane >> 4) & 1) * 8 + (lane & 7);
    const int bseg   = ((lane >> 3) & 1) * 16;

    for (int t = 0; t < T; t++) {
        const int bf = t & 1;
        // stage(t) was committed a full tap ago -> latency already hidden.
        asm volatile("cp.async.wait_group 0;" ::: "memory");
        // ONE barrier: (a) stage(t) copies from all threads visible,
        // (b) all warps finished compute(t-1), so buffer bf^1 is reusable.
        __syncthreads();
        if (t + 1 < T) stage(t + 1, bf ^ 1);

        const uint32_t abase = sb + SM_A + bf * 32768;
        const uint32_t bbase = sb + SM_B + bf * 8192;

        #pragma unroll
        for (int kk = 0; kk < 4; kk++) {
            uint32_t Af[2][4];
            const uint32_t acol = kk * 32 + aseg;
            #pragma unroll
            for (int i = 0; i < 2; i++)
                ldsm4(Af[i], abase + SWZ((wrp * 32 + i * 16 + arow_s) * 128 + acol));
            #pragma unroll
            for (int jp = 0; jp < 4; jp++) {
                uint32_t Bf[4];
                ldsm4(Bf, bbase + SWZ((jp * 16 + brow_s) * 128 + kk * 32 + bseg));
                #pragma unroll
                for (int i = 0; i < 2; i++) {
                    mma_f16(acc[i][2 * jp],     Af[i], Bf[0], Bf[1]);
                    mma_f16(acc[i][2 * jp + 1], Af[i], Bf[2], Bf[3]);
                }
            }
        }
    }

    // epilogue: bias, strided scatter into the class sub-grid
    float* ob = out + (size_t)b * OSB;
    const int gbase = tile * 256 + wrp * 32 + (lane >> 2);
    #pragma unroll
    for (int i = 0; i < 2; i++) {
        #pragma unroll
        for (int h = 0; h < 2; h++) {
            int g = gbase + i * 16 + h * 8;
            if (g >= Ntot) continue;
            int m4 = g % n4; int q = g / n4;
            int m3 = q % n3; q /= n3;
            int m2 = q % n2; int m1 = q / n2;
            long o = (long)(2 * m1 + p1) * OS1 + (2 * m2 + p2) * OS2 +
                     (2 * m3 + p3) * OS3 + (2 * m4 + p4);
            float* op = ob + o;
            #pragma unroll
            for (int j = 0; j < 8; j++) {
                int co = j * 8 + (lane & 3) * 2;
                op[(size_t)co * OSC]       = acc[i][j][2 * h]     + bs[co];
                op[(size_t)(co + 1) * OSC] = acc[i][j][2 * h + 1] + bs[co + 1];
            }
        }
    }
}

extern "C" void kernel_launch(void* const* d_in, const int* in_sizes, int n_in,
                              void* d_out, int out_size) {
    const float* x    = (const float*)d_in[0];
    const float* w    = (const float*)d_in[1];
    const float* bias = (const float*)d_in[2];
    float* out = (float*)d_out;

    cudaFuncSetAttribute(ct4d_mma, cudaFuncAttributeMaxDynamicSharedMemorySize, SM_TOTAL);

    prep_all<<<3888, 256>>>(w, x);
    // 112 = ceil(13^4 / 256); smaller classes early-exit surplus tiles.
    ct4d_mma<<<dim3(112, 4, 16), 256, SM_TOTAL>>>(bias, out);
}